// round 12
// baseline (speedup 1.0000x reference)
#include <cuda_runtime.h>
#include <math.h>
#include <stdint.h>

// ---------------------------------------------------------------------------
// ToRGB: out = tanh( (x * s[b]) @ k2d + bias ),  s = (w@affine_w + affine_b)/sqrt(512)
// Fold: keff[b,c,o] = s[b,c] * k2d[c,o]
// Main: per-warp self-service cp.async pipeline (3-stage ring, depth-2
// prefetch), keff in registers (f32x2 pairs), 2 CTAs/SM single wave.
// ---------------------------------------------------------------------------

#define B_    8
#define CIN   512
#define WDIM  128
#define COUT  4
#define PIX   (128*128)
#define INV_SQRT_CIN 0.04419417382415922f

#define GRID_X   37                 // 37*8 = 296 = 148 SMs * 2 CTAs
#define UNITS    (PIX / 8)          // 2048 units of 8 px (1 px per warp)
#define STAGES   3

typedef unsigned long long u64;

// folded per-batch kernel, PLAIN channel order: g_keff[b*CIN + c] = s*k2d[c]
__device__ float4 g_keff[B_ * CIN];

// ---------------------------------------------------------------------------
// Prologue: grid=(8,8), block=(64,8).
// ---------------------------------------------------------------------------
__global__ void build_keff_kernel(const float* __restrict__ w,
                                  const float* __restrict__ affine_w,
                                  const float* __restrict__ affine_b,
                                  const float* __restrict__ k2d)
{
    const int b  = blockIdx.x;
    const int c  = blockIdx.y * 64 + threadIdx.x;
    const int js = threadIdx.y;                    // 0..7

    __shared__ float ws[WDIM];
    __shared__ float part[7][64];

    const int tid = threadIdx.y * 64 + threadIdx.x;
    if (tid < WDIM) ws[tid] = w[b * WDIM + tid];
    __syncthreads();

    float s = 0.f;
    const int j0 = js * 16;
    #pragma unroll
    for (int j = j0; j < j0 + 16; j++)
        s = fmaf(ws[j], affine_w[j * CIN + c], s);

    if (js > 0) part[js - 1][threadIdx.x] = s;
    __syncthreads();

    if (js == 0) {
        #pragma unroll
        for (int q = 0; q < 7; q++) s += part[q][threadIdx.x];
        s = (s + affine_b[c]) * INV_SQRT_CIN;
        float4 kk = *reinterpret_cast<const float4*>(k2d + c * COUT);
        float4 o;
        o.x = s * kk.x; o.y = s * kk.y; o.z = s * kk.z; o.w = s * kk.w;
        g_keff[b * CIN + c] = o;
    }
}

// ---------------------------------------------------------------------------
// helpers
// ---------------------------------------------------------------------------
__device__ __forceinline__ uint32_t smem_u32(const void* p) {
    uint32_t a;
    asm("{ .reg .u64 t; cvta.to.shared.u64 t, %1; cvt.u32.u64 %0, t; }"
        : "=r"(a) : "l"(p));
    return a;
}
__device__ __forceinline__ void cp16(uint32_t dst, const void* src) {
    asm volatile("cp.async.cg.shared.global [%0], [%1], 16;"
                 :: "r"(dst), "l"(src) : "memory");
}
__device__ __forceinline__ void cp_commit() {
    asm volatile("cp.async.commit_group;" ::: "memory");
}
__device__ __forceinline__ void cp_wait2() {
    asm volatile("cp.async.wait_group 2;" ::: "memory");
}
__device__ __forceinline__ u64 pack_f32x2(float lo, float hi) {
    u64 r;
    asm("mov.b64 %0, {%1, %2};" : "=l"(r) : "f"(lo), "f"(hi));
    return r;
}
__device__ __forceinline__ void unpack_f32x2(float& lo, float& hi, u64 v) {
    asm("mov.b64 {%0, %1}, %2;" : "=f"(lo), "=f"(hi) : "l"(v));
}
__device__ __forceinline__ u64 fma_f32x2(u64 a, u64 b, u64 c) {
    u64 d;
    asm("fma.rn.f32x2 %0, %1, %2, %3;" : "=l"(d) : "l"(a), "l"(b), "l"(c));
    return d;
}
__device__ __forceinline__ float tanh_fast(float x) {
    float r;
    asm("tanh.approx.f32 %0, %1;" : "=f"(r) : "f"(x));
    return r;
}
__device__ __forceinline__ float pairstep(float a, float b, bool lo, int off)
{
    float send = lo ? b : a;
    float recv = __shfl_xor_sync(0xffffffffu, send, off);
    return (lo ? a : b) + recv;
}

// ---------------------------------------------------------------------------
// Main: grid=(37, 8), block=256 (8 warps), 2 CTAs/SM — one wave.
// Warp owns 1 px per unit; cp.async self-service ring, keff in registers.
// ---------------------------------------------------------------------------
__global__ void __launch_bounds__(256, 2)
torgb_main_kernel(const float* __restrict__ x,
                  const float* __restrict__ bias,
                  float* __restrict__ out)
{
    // per-warp 3-stage ring: [warp][stage][128 float4] = 48 KB
    __shared__ __align__(16) float4 ring[8][STAGES][CIN / 4];

    const int b    = blockIdx.y;
    const int warp = threadIdx.x >> 5;
    const int lane = threadIdx.x & 31;

    // ---- keff into registers as f32x2 pairs: channels c = lane*4 + j + i*128
    u64 kxy[4][4], kzw[4][4];
    {
        const float4* gk = g_keff + b * CIN;
        #pragma unroll
        for (int i = 0; i < 4; i++)
            #pragma unroll
            for (int j = 0; j < 4; j++) {
                float4 kv = __ldg(gk + lane * 4 + j + i * 128);
                kxy[i][j] = pack_f32x2(kv.x, kv.y);
                kzw[i][j] = pack_f32x2(kv.z, kv.w);
            }
    }

    // reduce lane map (R4-verified): lanes 0,8,16,24 hold o0..o3
    const int   o_idx  = lane >> 3;
    const bool  storer = (lane & 7) == 0;
    const float mybias = bias[o_idx & 3];
    const bool  lo16 = (lane & 16) == 0;
    const bool  lo8  = (lane & 8)  == 0;

    // smem ring base for this warp+lane (byte address), stage stride 2048 B
    const uint32_t ring0 = smem_u32(&ring[warp][0][0]) + (uint32_t)lane * 16u;

    // iteration k computes unit u = blockIdx.x + k*GRID_X, pixel = u*8 + warp
    const int n_iter = (UNITS - 1 - blockIdx.x) / GRID_X + 1;

    const long long px0   = (long long)b * PIX + (long long)blockIdx.x * 8 + warp;
    const long long pxstep = (long long)GRID_X * 8;              // pixels per k
    const char* xload = (const char*)(x + px0 * CIN) + (uint32_t)lane * 16u;
    const long long xstep = pxstep * CIN * 4;                    // bytes per k
    float* op = out + px0 * COUT + o_idx;
    const long long ostep = pxstep * COUT;

    // ---- prologue: issue k = 0, 1 ----
    #pragma unroll
    for (int k = 0; k < 2; k++) {
        if (k < n_iter) {
            const uint32_t dst = ring0 + (uint32_t)k * 2048u;
            const char* src = xload + (long long)k * xstep;
            #pragma unroll
            for (int i = 0; i < 4; i++)
                cp16(dst + i * 512u, src + i * 512);
        }
        cp_commit();
    }

    int s_load = 2, s_comp = 0;
    const char* xld = xload + 2 * xstep;

    #pragma unroll 1
    for (int k = 0; k < n_iter; k++) {
        // ---- issue k+2 (guarded), always commit ----
        if (k + 2 < n_iter) {
            const uint32_t dst = ring0 + (uint32_t)s_load * 2048u;
            #pragma unroll
            for (int i = 0; i < 4; i++)
                cp16(dst + i * 512u, xld + i * 512);
        }
        cp_commit();
        if (++s_load == STAGES) s_load = 0;
        xld += xstep;

        // ---- wait for group k, compute from stage s_comp ----
        cp_wait2();

        const float4* row = &ring[warp][s_comp][0] + lane;   // own bytes only
        u64 pa = 0ull, pb = 0ull;
        #pragma unroll
        for (int i = 0; i < 4; i++) {
            const float4 a = row[i * 32];                    // LDS.128
            const float av[4] = {a.x, a.y, a.z, a.w};
            #pragma unroll
            for (int j = 0; j < 4; j++) {
                const u64 ap = pack_f32x2(av[j], av[j]);
                pa = fma_f32x2(ap, kxy[i][j], pa);
                pb = fma_f32x2(ap, kzw[i][j], pb);
            }
        }
        if (++s_comp == STAGES) s_comp = 0;

        float v0, v1, v2, v3;
        unpack_f32x2(v0, v1, pa);
        unpack_f32x2(v2, v3, pb);

        // ---- 1-px packed reduce: 6 shuffles ----
        float r0 = pairstep(v0, v2, lo16, 16);
        float r1 = pairstep(v1, v3, lo16, 16);
        float t  = pairstep(r0, r1, lo8, 8);
        t += __shfl_xor_sync(0xffffffffu, t, 4);
        t += __shfl_xor_sync(0xffffffffu, t, 2);
        t += __shfl_xor_sync(0xffffffffu, t, 1);
        // lanes 0,8,16,24 -> o0..o3

        if (storer)
            *op = tanh_fast(t + mybias);
        op += ostep;
    }
}

// ---------------------------------------------------------------------------
// inputs: x[8,128,128,512], w[8,128], affine_w[128,512], affine_b[512],
//         kernel[1,1,512,4], bias[4]  -> out[8,128,128,4] f32
// ---------------------------------------------------------------------------
extern "C" void kernel_launch(void* const* d_in, const int* in_sizes, int n_in,
                              void* d_out, int out_size)
{
    const float* x        = (const float*)d_in[0];
    const float* w        = (const float*)d_in[1];
    const float* affine_w = (const float*)d_in[2];
    const float* affine_b = (const float*)d_in[3];
    const float* k2d      = (const float*)d_in[4];
    const float* bias     = (const float*)d_in[5];
    float*       out      = (float*)d_out;

    dim3 pgrid(B_, 8), pblock(64, 8);
    build_keff_kernel<<<pgrid, pblock>>>(w, affine_w, affine_b, k2d);

    dim3 grid(GRID_X, B_);
    torgb_main_kernel<<<grid, 256>>>(x, bias, out);
}

// round 13
// speedup vs baseline: 1.0061x; 1.0061x over previous
#include <cuda_runtime.h>
#include <math.h>

// ---------------------------------------------------------------------------
// ToRGB: out = tanh( (x * s[b]) @ k2d + bias ),  s = (w@affine_w + affine_b)/sqrt(512)
// Fold: keff[b,c,o] = s[b,c] * k2d[c,o]
// Main: champion R10 body (2 px/warp, f32x2 FMA, 9-shuffle packed reduce,
// tanh.approx), single-wave grid 74x8, 4 CTAs/SM + L2::256B prefetch loads.
// ---------------------------------------------------------------------------

#define B_    8
#define CIN   512
#define WDIM  128
#define COUT  4
#define PIX   (128*128)
#define INV_SQRT_CIN 0.04419417382415922f

#define GRID_X          74               // 74*8 = 592 = 148 SMs * 4 CTAs
#define UNIT_PX         16               // 8 warps * 2 px
#define UNITS_PER_BATCH (PIX / UNIT_PX)  // 1024

typedef unsigned long long u64;

// folded per-batch kernel, PERMUTED (R6 scheme):
// c = lane*4 + j + i*128  ->  idx = (i*4 + j)*32 + lane
__device__ float4 g_keff[B_ * CIN];

// ---------------------------------------------------------------------------
// Prologue: grid=(8,8), block=(64,8). 64-channel chunks, 8 j-slices of 16.
// ---------------------------------------------------------------------------
__global__ void build_keff_kernel(const float* __restrict__ w,
                                  const float* __restrict__ affine_w,
                                  const float* __restrict__ affine_b,
                                  const float* __restrict__ k2d)
{
    const int b  = blockIdx.x;
    const int c  = blockIdx.y * 64 + threadIdx.x;
    const int js = threadIdx.y;                    // 0..7

    __shared__ float ws[WDIM];
    __shared__ float part[7][64];

    const int tid = threadIdx.y * 64 + threadIdx.x;
    if (tid < WDIM) ws[tid] = w[b * WDIM + tid];
    __syncthreads();

    float s = 0.f;
    const int j0 = js * 16;
    #pragma unroll
    for (int j = j0; j < j0 + 16; j++)
        s = fmaf(ws[j], affine_w[j * CIN + c], s);

    if (js > 0) part[js - 1][threadIdx.x] = s;
    __syncthreads();

    if (js == 0) {
        #pragma unroll
        for (int q = 0; q < 7; q++) s += part[q][threadIdx.x];
        s = (s + affine_b[c]) * INV_SQRT_CIN;
        float4 kk = *reinterpret_cast<const float4*>(k2d + c * COUT);
        float4 o;
        o.x = s * kk.x; o.y = s * kk.y; o.z = s * kk.z; o.w = s * kk.w;
        const int i = c >> 7, r = c & 127, lane = r >> 2, jj = r & 3;
        g_keff[b * CIN + (i * 4 + jj) * 32 + lane] = o;
    }
}

// ---------------------------------------------------------------------------
// helpers
// ---------------------------------------------------------------------------
__device__ __forceinline__ float4 ldg_cs_pf256(const float4* p) {
    float4 v;
    asm volatile("ld.global.cs.L2::256B.v4.f32 {%0, %1, %2, %3}, [%4];"
                 : "=f"(v.x), "=f"(v.y), "=f"(v.z), "=f"(v.w) : "l"(p));
    return v;
}
__device__ __forceinline__ u64 pack_f32x2(float lo, float hi) {
    u64 r;
    asm("mov.b64 %0, {%1, %2};" : "=l"(r) : "f"(lo), "f"(hi));
    return r;
}
__device__ __forceinline__ void unpack_f32x2(float& lo, float& hi, u64 v) {
    asm("mov.b64 {%0, %1}, %2;" : "=f"(lo), "=f"(hi) : "l"(v));
}
__device__ __forceinline__ u64 fma_f32x2(u64 a, u64 b, u64 c) {
    u64 d;
    asm("fma.rn.f32x2 %0, %1, %2, %3;" : "=l"(d) : "l"(a), "l"(b), "l"(c));
    return d;
}
__device__ __forceinline__ float tanh_fast(float x) {
    float r;
    asm("tanh.approx.f32 %0, %1;" : "=f"(r) : "f"(x));
    return r;
}
// packed pair reduction: two independent sums, one shuffle
__device__ __forceinline__ float pairstep(float a, float b, bool lo, int off)
{
    float send = lo ? b : a;
    float recv = __shfl_xor_sync(0xffffffffu, send, off);
    return (lo ? a : b) + recv;
}

// ---------------------------------------------------------------------------
// Main: grid=(74, 8), block=256 (8 warps), 4 CTAs/SM — one wave.
// Warp: 2 px per unit; f32x2-packed FMA; 9-shuffle packed reduce.
// ---------------------------------------------------------------------------
__global__ void __launch_bounds__(256, 4)
torgb_main_kernel(const float* __restrict__ x,
                  const float* __restrict__ bias,
                  float* __restrict__ out)
{
    const int b    = blockIdx.y;
    const int warp = threadIdx.x >> 5;
    const int lane = threadIdx.x & 31;

    __shared__ __align__(16) float4 kws[CIN];   // 8 KB

    {
        const float4* gk = g_keff + b * CIN;
        kws[threadIdx.x]       = gk[threadIdx.x];
        kws[threadIdx.x + 256] = gk[threadIdx.x + 256];
    }
    __syncthreads();

    // keff as packed pairs: kwl2[idx].x = (k.x,k.y), .y = (k.z,k.w)
    const ulonglong2* kwl2 = reinterpret_cast<const ulonglong2*>(kws) + lane;

    // final packed-reduce slots (R2/R6-verified):
    // lanes with (lane&3)==0 store pixel p_off=bit4, output o_idx.
    const int   p_off  = (lane >> 4) & 1;
    const int   o_idx  = (((lane >> 2) & 1) << 1) | ((lane >> 3) & 1);
    const bool  storer = (lane & 3) == 0;
    const float mybias = bias[o_idx];
    const bool  lo16 = lane < 16;
    const bool  lo8  = (lane & 8) == 0;
    const bool  lo4  = (lane & 4) == 0;

    const long long px0 = (long long)b * PIX + (long long)blockIdx.x * UNIT_PX + warp * 2;
    const float4* xp = reinterpret_cast<const float4*>(x + px0 * CIN) + lane;
    float*        op = out + px0 * COUT + p_off * COUT + o_idx;

    const long long xstep = (long long)GRID_X * UNIT_PX * (CIN / 4);
    const long long ostep = (long long)GRID_X * UNIT_PX * COUT;

    #pragma unroll 1
    for (int u = blockIdx.x; u < UNITS_PER_BATCH; u += GRID_X) {
        // ---- 2 pixels: 8 independent LDG.128 with L2::256B prefetch ----
        float4 a[4], c4[4];
        #pragma unroll
        for (int i = 0; i < 4; i++) a[i]  = ldg_cs_pf256(xp + i * 32);
        #pragma unroll
        for (int i = 0; i < 4; i++) c4[i] = ldg_cs_pf256(xp + 128 + i * 32);

        // packed accumulators: p0a=(v0,v1) p0b=(v2,v3) p1a=(v4,v5) p1b=(v6,v7)
        u64 p0a = 0ull, p0b = 0ull, p1a = 0ull, p1b = 0ull;

        #pragma unroll
        for (int i = 0; i < 4; i++) {
            const float av[4] = {a[i].x,  a[i].y,  a[i].z,  a[i].w};
            const float cv[4] = {c4[i].x, c4[i].y, c4[i].z, c4[i].w};
            u64 ap[4], cp[4];
            #pragma unroll
            for (int j = 0; j < 4; j++) {
                ap[j] = pack_f32x2(av[j], av[j]);
                cp[j] = pack_f32x2(cv[j], cv[j]);
            }
            #pragma unroll
            for (int j = 0; j < 4; j++) {
                const ulonglong2 kk = kwl2[(i * 4 + j) * 32];   // LDS.128
                p0a = fma_f32x2(ap[j], kk.x, p0a);
                p0b = fma_f32x2(ap[j], kk.y, p0b);
                p1a = fma_f32x2(cp[j], kk.x, p1a);
                p1b = fma_f32x2(cp[j], kk.y, p1b);
            }
        }

        float v0, v1, v2, v3, v4, v5, v6, v7;
        unpack_f32x2(v0, v1, p0a);
        unpack_f32x2(v2, v3, p0b);
        unpack_f32x2(v4, v5, p1a);
        unpack_f32x2(v6, v7, p1b);

        // ---- packed butterfly: 8 sums in 9 shuffles (R6-verified) ----
        float r0 = pairstep(v0, v4, lo16, 16);
        float r1 = pairstep(v1, v5, lo16, 16);
        float r2 = pairstep(v2, v6, lo16, 16);
        float r3 = pairstep(v3, v7, lo16, 16);

        float s0 = pairstep(r0, r1, lo8, 8);
        float s1 = pairstep(r2, r3, lo8, 8);

        float t  = pairstep(s0, s1, lo4, 4);
        t += __shfl_xor_sync(0xffffffffu, t, 2);
        t += __shfl_xor_sync(0xffffffffu, t, 1);

        if (storer)
            *op = tanh_fast(t + mybias);

        xp += xstep;
        op += ostep;
    }
}

// ---------------------------------------------------------------------------
// inputs: x[8,128,128,512], w[8,128], affine_w[128,512], affine_b[512],
//         kernel[1,1,512,4], bias[4]  -> out[8,128,128,4] f32
// ---------------------------------------------------------------------------
extern "C" void kernel_launch(void* const* d_in, const int* in_sizes, int n_in,
                              void* d_out, int out_size)
{
    const float* x        = (const float*)d_in[0];
    const float* w        = (const float*)d_in[1];
    const float* affine_w = (const float*)d_in[2];
    const float* affine_b = (const float*)d_in[3];
    const float* k2d      = (const float*)d_in[4];
    const float* bias     = (const float*)d_in[5];
    float*       out      = (float*)d_out;

    dim3 pgrid(B_, 8), pblock(64, 8);
    build_keff_kernel<<<pgrid, pblock>>>(w, affine_w, affine_b, k2d);

    dim3 grid(GRID_X, B_);
    torgb_main_kernel<<<grid, 256>>>(x, bias, out);
}

// round 14
// speedup vs baseline: 1.0142x; 1.0081x over previous
#include <cuda_runtime.h>
#include <math.h>

// ---------------------------------------------------------------------------
// ToRGB: out = tanh( (x * s[b]) @ k2d + bias ),  s = (w@affine_w + affine_b)/sqrt(512)
// Fold: keff[b,c,o] = s[b,c] * k2d[c,o]
// CHAMPION (R10): 2-px/warp body, f32x2-packed FMA, tanh.approx,
// 9-shuffle packed reduce, persistent single-wave grid (74 x 8), 4 CTAs/SM.
// Measured: 45.8 us total, main 44.67 us @ DRAM 77% (6.1 TB/s) — at the
// empirically-established HBM streaming ceiling for this access pattern.
// ---------------------------------------------------------------------------

#define B_    8
#define CIN   512
#define WDIM  128
#define COUT  4
#define PIX   (128*128)
#define INV_SQRT_CIN 0.04419417382415922f

#define GRID_X          74               // 74*8 = 592 = 148 SMs * 4 CTAs
#define UNIT_PX         16               // 8 warps * 2 px
#define UNITS_PER_BATCH (PIX / UNIT_PX)  // 1024

typedef unsigned long long u64;

// folded per-batch kernel, PERMUTED (R6 scheme):
// c = lane*4 + j + i*128  ->  idx = (i*4 + j)*32 + lane
__device__ float4 g_keff[B_ * CIN];

// ---------------------------------------------------------------------------
// Prologue: grid=(8,8), block=(64,8). 64-channel chunks, 8 j-slices of 16.
// ---------------------------------------------------------------------------
__global__ void build_keff_kernel(const float* __restrict__ w,
                                  const float* __restrict__ affine_w,
                                  const float* __restrict__ affine_b,
                                  const float* __restrict__ k2d)
{
    const int b  = blockIdx.x;
    const int c  = blockIdx.y * 64 + threadIdx.x;
    const int js = threadIdx.y;                    // 0..7

    __shared__ float ws[WDIM];
    __shared__ float part[7][64];

    const int tid = threadIdx.y * 64 + threadIdx.x;
    if (tid < WDIM) ws[tid] = w[b * WDIM + tid];
    __syncthreads();

    float s = 0.f;
    const int j0 = js * 16;
    #pragma unroll
    for (int j = j0; j < j0 + 16; j++)
        s = fmaf(ws[j], affine_w[j * CIN + c], s);

    if (js > 0) part[js - 1][threadIdx.x] = s;
    __syncthreads();

    if (js == 0) {
        #pragma unroll
        for (int q = 0; q < 7; q++) s += part[q][threadIdx.x];
        s = (s + affine_b[c]) * INV_SQRT_CIN;
        float4 kk = *reinterpret_cast<const float4*>(k2d + c * COUT);
        float4 o;
        o.x = s * kk.x; o.y = s * kk.y; o.z = s * kk.z; o.w = s * kk.w;
        const int i = c >> 7, r = c & 127, lane = r >> 2, jj = r & 3;
        g_keff[b * CIN + (i * 4 + jj) * 32 + lane] = o;
    }
}

// ---------------------------------------------------------------------------
// f32x2 packed math helpers (sm_103a)
// ---------------------------------------------------------------------------
__device__ __forceinline__ u64 pack_f32x2(float lo, float hi) {
    u64 r;
    asm("mov.b64 %0, {%1, %2};" : "=l"(r) : "f"(lo), "f"(hi));
    return r;
}
__device__ __forceinline__ void unpack_f32x2(float& lo, float& hi, u64 v) {
    asm("mov.b64 {%0, %1}, %2;" : "=f"(lo), "=f"(hi) : "l"(v));
}
__device__ __forceinline__ u64 fma_f32x2(u64 a, u64 b, u64 c) {
    u64 d;
    asm("fma.rn.f32x2 %0, %1, %2, %3;" : "=l"(d) : "l"(a), "l"(b), "l"(c));
    return d;
}
__device__ __forceinline__ float tanh_fast(float x) {
    float r;
    asm("tanh.approx.f32 %0, %1;" : "=f"(r) : "f"(x));
    return r;
}

// packed pair reduction: two independent sums, one shuffle
__device__ __forceinline__ float pairstep(float a, float b, bool lo, int off)
{
    float send = lo ? b : a;
    float recv = __shfl_xor_sync(0xffffffffu, send, off);
    return (lo ? a : b) + recv;
}

// ---------------------------------------------------------------------------
// Main: grid=(74, 8), block=256 (8 warps), 4 CTAs/SM — one wave.
// Warp: 2 px per unit; f32x2-packed FMA; 9-shuffle packed reduce.
// ---------------------------------------------------------------------------
__global__ void __launch_bounds__(256, 4)
torgb_main_kernel(const float* __restrict__ x,
                  const float* __restrict__ bias,
                  float* __restrict__ out)
{
    const int b    = blockIdx.y;
    const int warp = threadIdx.x >> 5;
    const int lane = threadIdx.x & 31;

    __shared__ __align__(16) float4 kws[CIN];   // 8 KB

    {
        const float4* gk = g_keff + b * CIN;
        kws[threadIdx.x]       = gk[threadIdx.x];
        kws[threadIdx.x + 256] = gk[threadIdx.x + 256];
    }
    __syncthreads();

    // keff as packed pairs: kwl2[idx].x = (k.x,k.y), .y = (k.z,k.w)
    const ulonglong2* kwl2 = reinterpret_cast<const ulonglong2*>(kws) + lane;

    // final packed-reduce slots (R2/R6-verified):
    // lanes with (lane&3)==0 store pixel p_off=bit4, output o_idx.
    const int   p_off  = (lane >> 4) & 1;
    const int   o_idx  = (((lane >> 2) & 1) << 1) | ((lane >> 3) & 1);
    const bool  storer = (lane & 3) == 0;
    const float mybias = bias[o_idx];
    const bool  lo16 = lane < 16;
    const bool  lo8  = (lane & 8) == 0;
    const bool  lo4  = (lane & 4) == 0;

    const long long px0 = (long long)b * PIX + (long long)blockIdx.x * UNIT_PX + warp * 2;
    const float4* xp = reinterpret_cast<const float4*>(x + px0 * CIN) + lane;
    float*        op = out + px0 * COUT + p_off * COUT + o_idx;

    const long long xstep = (long long)GRID_X * UNIT_PX * (CIN / 4);
    const long long ostep = (long long)GRID_X * UNIT_PX * COUT;

    #pragma unroll 1
    for (int u = blockIdx.x; u < UNITS_PER_BATCH; u += GRID_X) {
        // ---- 2 pixels: 8 independent LDG.128 ----
        float4 a[4], c4[4];
        #pragma unroll
        for (int i = 0; i < 4; i++) a[i]  = __ldcs(xp + i * 32);
        #pragma unroll
        for (int i = 0; i < 4; i++) c4[i] = __ldcs(xp + 128 + i * 32);

        // packed accumulators: p0a=(v0,v1) p0b=(v2,v3) p1a=(v4,v5) p1b=(v6,v7)
        u64 p0a = 0ull, p0b = 0ull, p1a = 0ull, p1b = 0ull;

        #pragma unroll
        for (int i = 0; i < 4; i++) {
            const float av[4] = {a[i].x,  a[i].y,  a[i].z,  a[i].w};
            const float cv[4] = {c4[i].x, c4[i].y, c4[i].z, c4[i].w};
            u64 ap[4], cp[4];
            #pragma unroll
            for (int j = 0; j < 4; j++) {
                ap[j] = pack_f32x2(av[j], av[j]);
                cp[j] = pack_f32x2(cv[j], cv[j]);
            }
            #pragma unroll
            for (int j = 0; j < 4; j++) {
                const ulonglong2 kk = kwl2[(i * 4 + j) * 32];   // LDS.128
                p0a = fma_f32x2(ap[j], kk.x, p0a);
                p0b = fma_f32x2(ap[j], kk.y, p0b);
                p1a = fma_f32x2(cp[j], kk.x, p1a);
                p1b = fma_f32x2(cp[j], kk.y, p1b);
            }
        }

        float v0, v1, v2, v3, v4, v5, v6, v7;
        unpack_f32x2(v0, v1, p0a);
        unpack_f32x2(v2, v3, p0b);
        unpack_f32x2(v4, v5, p1a);
        unpack_f32x2(v6, v7, p1b);

        // ---- packed butterfly: 8 sums in 9 shuffles (R6-verified) ----
        float r0 = pairstep(v0, v4, lo16, 16);
        float r1 = pairstep(v1, v5, lo16, 16);
        float r2 = pairstep(v2, v6, lo16, 16);
        float r3 = pairstep(v3, v7, lo16, 16);

        float s0 = pairstep(r0, r1, lo8, 8);
        float s1 = pairstep(r2, r3, lo8, 8);

        float t  = pairstep(s0, s1, lo4, 4);
        t += __shfl_xor_sync(0xffffffffu, t, 2);
        t += __shfl_xor_sync(0xffffffffu, t, 1);

        if (storer)
            *op = tanh_fast(t + mybias);

        xp += xstep;
        op += ostep;
    }
}

// ---------------------------------------------------------------------------
// inputs: x[8,128,128,512], w[8,128], affine_w[128,512], affine_b[512],
//         kernel[1,1,512,4], bias[4]  -> out[8,128,128,4] f32
// ---------------------------------------------------------------------------
extern "C" void kernel_launch(void* const* d_in, const int* in_sizes, int n_in,
                              void* d_out, int out_size)
{
    const float* x        = (const float*)d_in[0];
    const float* w        = (const float*)d_in[1];
    const float* affine_w = (const float*)d_in[2];
    const float* affine_b = (const float*)d_in[3];
    const float* k2d      = (const float*)d_in[4];
    const float* bias     = (const float*)d_in[5];
    float*       out      = (float*)d_out;

    dim3 pgrid(B_, 8), pblock(64, 8);
    build_keff_kernel<<<pgrid, pblock>>>(w, affine_w, affine_b, k2d);

    dim3 grid(GRID_X, B_);
    torgb_main_kernel<<<grid, 256>>>(x, bias, out);
}

// round 15
// speedup vs baseline: 1.0513x; 1.0365x over previous
#include <cuda_runtime.h>
#include <math.h>

// ---------------------------------------------------------------------------
// ToRGB: out = tanh( (x * s[b]) @ k2d + bias ),  s = (w@affine_w + affine_b)/sqrt(512)
// Fold: keff[b,c,o] = s[b,c] * k2d[c,o]
// CHAMPION body (R10: 2 px/warp, f32x2 FMA, tanh.approx, 9-shuffle reduce,
// single-wave 74x8 grid, 4 CTAs/SM) + PDL: main launches programmatically
// dependent on the prologue, issues its first x loads BEFORE the dependency
// sync so prologue/launch overhead hides under main's first DRAM fetches.
// ---------------------------------------------------------------------------

#define B_    8
#define CIN   512
#define WDIM  128
#define COUT  4
#define PIX   (128*128)
#define INV_SQRT_CIN 0.04419417382415922f

#define GRID_X          74               // 74*8 = 592 = 148 SMs * 4 CTAs
#define UNIT_PX         16               // 8 warps * 2 px
#define UNITS_PER_BATCH (PIX / UNIT_PX)  // 1024

typedef unsigned long long u64;

// folded per-batch kernel, PERMUTED (R6 scheme):
// c = lane*4 + j + i*128  ->  idx = (i*4 + j)*32 + lane
__device__ float4 g_keff[B_ * CIN];

// ---------------------------------------------------------------------------
// Prologue: grid=(8,8), block=(64,8). Triggers PDL completion early.
// ---------------------------------------------------------------------------
__global__ void build_keff_kernel(const float* __restrict__ w,
                                  const float* __restrict__ affine_w,
                                  const float* __restrict__ affine_b,
                                  const float* __restrict__ k2d)
{
    const int b  = blockIdx.x;
    const int c  = blockIdx.y * 64 + threadIdx.x;
    const int js = threadIdx.y;                    // 0..7

    __shared__ float ws[WDIM];
    __shared__ float part[7][64];

    const int tid = threadIdx.y * 64 + threadIdx.x;
    if (tid < WDIM) ws[tid] = w[b * WDIM + tid];
    __syncthreads();

    float s = 0.f;
    const int j0 = js * 16;
    #pragma unroll
    for (int j = j0; j < j0 + 16; j++)
        s = fmaf(ws[j], affine_w[j * CIN + c], s);

    if (js > 0) part[js - 1][threadIdx.x] = s;
    __syncthreads();

    if (js == 0) {
        #pragma unroll
        for (int q = 0; q < 7; q++) s += part[q][threadIdx.x];
        s = (s + affine_b[c]) * INV_SQRT_CIN;
        float4 kk = *reinterpret_cast<const float4*>(k2d + c * COUT);
        float4 o;
        o.x = s * kk.x; o.y = s * kk.y; o.z = s * kk.z; o.w = s * kk.w;
        const int i = c >> 7, r = c & 127, lane = r >> 2, jj = r & 3;
        g_keff[b * CIN + (i * 4 + jj) * 32 + lane] = o;
    }

#if __CUDA_ARCH__ >= 900
    cudaTriggerProgrammaticLaunchCompletion();
#endif
}

// ---------------------------------------------------------------------------
// f32x2 packed math helpers (sm_103a)
// ---------------------------------------------------------------------------
__device__ __forceinline__ u64 pack_f32x2(float lo, float hi) {
    u64 r;
    asm("mov.b64 %0, {%1, %2};" : "=l"(r) : "f"(lo), "f"(hi));
    return r;
}
__device__ __forceinline__ void unpack_f32x2(float& lo, float& hi, u64 v) {
    asm("mov.b64 {%0, %1}, %2;" : "=f"(lo), "=f"(hi) : "l"(v));
}
__device__ __forceinline__ u64 fma_f32x2(u64 a, u64 b, u64 c) {
    u64 d;
    asm("fma.rn.f32x2 %0, %1, %2, %3;" : "=l"(d) : "l"(a), "l"(b), "l"(c));
    return d;
}
__device__ __forceinline__ float tanh_fast(float x) {
    float r;
    asm("tanh.approx.f32 %0, %1;" : "=f"(r) : "f"(x));
    return r;
}

// packed pair reduction: two independent sums, one shuffle
__device__ __forceinline__ float pairstep(float a, float b, bool lo, int off)
{
    float send = lo ? b : a;
    float recv = __shfl_xor_sync(0xffffffffu, send, off);
    return (lo ? a : b) + recv;
}

// ---------------------------------------------------------------------------
// Main: grid=(74, 8), block=256 (8 warps), 4 CTAs/SM — one wave.
// PDL: first unit's x loads issue BEFORE cudaGridDependencySynchronize().
// ---------------------------------------------------------------------------
__global__ void __launch_bounds__(256, 4)
torgb_main_kernel(const float* __restrict__ x,
                  const float* __restrict__ bias,
                  float* __restrict__ out)
{
    const int b    = blockIdx.y;
    const int warp = threadIdx.x >> 5;
    const int lane = threadIdx.x & 31;

    __shared__ __align__(16) float4 kws[CIN];   // 8 KB

    // ---- pointer setup (independent of keff) ----
    const int   p_off  = (lane >> 4) & 1;
    const int   o_idx  = (((lane >> 2) & 1) << 1) | ((lane >> 3) & 1);
    const bool  storer = (lane & 3) == 0;
    const bool  lo16 = lane < 16;
    const bool  lo8  = (lane & 8) == 0;
    const bool  lo4  = (lane & 4) == 0;

    const long long px0 = (long long)b * PIX + (long long)blockIdx.x * UNIT_PX + warp * 2;
    const float4* xp = reinterpret_cast<const float4*>(x + px0 * CIN) + lane;
    float*        op = out + px0 * COUT + p_off * COUT + o_idx;

    const long long xstep = (long long)GRID_X * UNIT_PX * (CIN / 4);
    const long long ostep = (long long)GRID_X * UNIT_PX * COUT;

    // ---- preload first unit's x (does NOT depend on prologue) ----
    float4 a[4], c4[4];
    #pragma unroll
    for (int i = 0; i < 4; i++) a[i]  = __ldcs(xp + i * 32);
    #pragma unroll
    for (int i = 0; i < 4; i++) c4[i] = __ldcs(xp + 128 + i * 32);

    // ---- wait for prologue's g_keff writes, then stage keff in smem ----
#if __CUDA_ARCH__ >= 900
    cudaGridDependencySynchronize();
#endif
    {
        const float4* gk = g_keff + b * CIN;
        kws[threadIdx.x]       = gk[threadIdx.x];
        kws[threadIdx.x + 256] = gk[threadIdx.x + 256];
    }
    __syncthreads();

    const ulonglong2* kwl2 = reinterpret_cast<const ulonglong2*>(kws) + lane;
    const float mybias = bias[o_idx];

    int u = blockIdx.x;
    #pragma unroll 1
    while (true) {
        // ---- FMA phase: consume preloaded a/c4 (f32x2 packed) ----
        u64 p0a = 0ull, p0b = 0ull, p1a = 0ull, p1b = 0ull;

        #pragma unroll
        for (int i = 0; i < 4; i++) {
            const float av[4] = {a[i].x,  a[i].y,  a[i].z,  a[i].w};
            const float cv[4] = {c4[i].x, c4[i].y, c4[i].z, c4[i].w};
            u64 ap[4], cp[4];
            #pragma unroll
            for (int j = 0; j < 4; j++) {
                ap[j] = pack_f32x2(av[j], av[j]);
                cp[j] = pack_f32x2(cv[j], cv[j]);
            }
            #pragma unroll
            for (int j = 0; j < 4; j++) {
                const ulonglong2 kk = kwl2[(i * 4 + j) * 32];   // LDS.128
                p0a = fma_f32x2(ap[j], kk.x, p0a);
                p0b = fma_f32x2(ap[j], kk.y, p0b);
                p1a = fma_f32x2(cp[j], kk.x, p1a);
                p1b = fma_f32x2(cp[j], kk.y, p1b);
            }
        }

        // ---- rotation: next unit's loads before the reduce chain ----
        const bool more = (u + GRID_X) < UNITS_PER_BATCH;
        xp += xstep;
        if (more) {
            #pragma unroll
            for (int i = 0; i < 4; i++) a[i]  = __ldcs(xp + i * 32);
            #pragma unroll
            for (int i = 0; i < 4; i++) c4[i] = __ldcs(xp + 128 + i * 32);
        }

        float v0, v1, v2, v3, v4, v5, v6, v7;
        unpack_f32x2(v0, v1, p0a);
        unpack_f32x2(v2, v3, p0b);
        unpack_f32x2(v4, v5, p1a);
        unpack_f32x2(v6, v7, p1b);

        // ---- packed butterfly: 8 sums in 9 shuffles (verified) ----
        float r0 = pairstep(v0, v4, lo16, 16);
        float r1 = pairstep(v1, v5, lo16, 16);
        float r2 = pairstep(v2, v6, lo16, 16);
        float r3 = pairstep(v3, v7, lo16, 16);

        float s0 = pairstep(r0, r1, lo8, 8);
        float s1 = pairstep(r2, r3, lo8, 8);

        float t  = pairstep(s0, s1, lo4, 4);
        t += __shfl_xor_sync(0xffffffffu, t, 2);
        t += __shfl_xor_sync(0xffffffffu, t, 1);

        if (storer)
            *op = tanh_fast(t + mybias);

        if (!more) break;
        op += ostep;
        u  += GRID_X;
    }
}

// ---------------------------------------------------------------------------
// inputs: x[8,128,128,512], w[8,128], affine_w[128,512], affine_b[512],
//         kernel[1,1,512,4], bias[4]  -> out[8,128,128,4] f32
// ---------------------------------------------------------------------------
extern "C" void kernel_launch(void* const* d_in, const int* in_sizes, int n_in,
                              void* d_out, int out_size)
{
    const float* x        = (const float*)d_in[0];
    const float* w        = (const float*)d_in[1];
    const float* affine_w = (const float*)d_in[2];
    const float* affine_b = (const float*)d_in[3];
    const float* k2d      = (const float*)d_in[4];
    const float* bias     = (const float*)d_in[5];
    float*       out      = (float*)d_out;

    dim3 pgrid(B_, 8), pblock(64, 8);
    build_keff_kernel<<<pgrid, pblock>>>(w, affine_w, affine_b, k2d);

    // main kernel with programmatic dependent launch (overlaps prologue tail)
    cudaLaunchConfig_t cfg = {};
    cfg.gridDim  = dim3(GRID_X, B_);
    cfg.blockDim = dim3(256);
    cfg.dynamicSmemBytes = 0;
    cfg.stream = 0;
    cudaLaunchAttribute at[1];
    at[0].id = cudaLaunchAttributeProgrammaticStreamSerialization;
    at[0].val.programmaticStreamSerializationAllowed = 1;
    cfg.attrs = at;
    cfg.numAttrs = 1;
    cudaLaunchKernelEx(&cfg, torgb_main_kernel, x, bias, out);
}

// round 16
// speedup vs baseline: 1.0580x; 1.0064x over previous
#include <cuda_runtime.h>
#include <math.h>

// ---------------------------------------------------------------------------
// ToRGB: out = tanh( (x * s[b]) @ k2d + bias ),  s = (w@affine_w + affine_b)/sqrt(512)
// Fold: keff[b,c,o] = s[b,c] * k2d[c,o]
// CHAMPION body (2 px/warp, f32x2 FMA, tanh.approx, 9-shuffle reduce,
// single-wave 74x8 grid, 4 CTAs/SM) + PDL overlap, widened with L2 prefetch
// of units 1-2 during the grid-dependency wait.
// ---------------------------------------------------------------------------

#define B_    8
#define CIN   512
#define WDIM  128
#define COUT  4
#define PIX   (128*128)
#define INV_SQRT_CIN 0.04419417382415922f

#define GRID_X          74               // 74*8 = 592 = 148 SMs * 4 CTAs
#define UNIT_PX         16               // 8 warps * 2 px
#define UNITS_PER_BATCH (PIX / UNIT_PX)  // 1024

typedef unsigned long long u64;

// folded per-batch kernel, PERMUTED (R6 scheme):
// c = lane*4 + j + i*128  ->  idx = (i*4 + j)*32 + lane
__device__ float4 g_keff[B_ * CIN];

// ---------------------------------------------------------------------------
// Prologue: grid=(8,8), block=(64,8). Triggers PDL completion early.
// ---------------------------------------------------------------------------
__global__ void build_keff_kernel(const float* __restrict__ w,
                                  const float* __restrict__ affine_w,
                                  const float* __restrict__ affine_b,
                                  const float* __restrict__ k2d)
{
    const int b  = blockIdx.x;
    const int c  = blockIdx.y * 64 + threadIdx.x;
    const int js = threadIdx.y;                    // 0..7

    __shared__ float ws[WDIM];
    __shared__ float part[7][64];

    const int tid = threadIdx.y * 64 + threadIdx.x;
    if (tid < WDIM) ws[tid] = w[b * WDIM + tid];
    __syncthreads();

    float s = 0.f;
    const int j0 = js * 16;
    #pragma unroll
    for (int j = j0; j < j0 + 16; j++)
        s = fmaf(ws[j], affine_w[j * CIN + c], s);

    if (js > 0) part[js - 1][threadIdx.x] = s;
    __syncthreads();

    if (js == 0) {
        #pragma unroll
        for (int q = 0; q < 7; q++) s += part[q][threadIdx.x];
        s = (s + affine_b[c]) * INV_SQRT_CIN;
        float4 kk = *reinterpret_cast<const float4*>(k2d + c * COUT);
        float4 o;
        o.x = s * kk.x; o.y = s * kk.y; o.z = s * kk.z; o.w = s * kk.w;
        const int i = c >> 7, r = c & 127, lane = r >> 2, jj = r & 3;
        g_keff[b * CIN + (i * 4 + jj) * 32 + lane] = o;
    }

#if __CUDA_ARCH__ >= 900
    cudaTriggerProgrammaticLaunchCompletion();
#endif
}

// ---------------------------------------------------------------------------
// helpers
// ---------------------------------------------------------------------------
__device__ __forceinline__ u64 pack_f32x2(float lo, float hi) {
    u64 r;
    asm("mov.b64 %0, {%1, %2};" : "=l"(r) : "f"(lo), "f"(hi));
    return r;
}
__device__ __forceinline__ void unpack_f32x2(float& lo, float& hi, u64 v) {
    asm("mov.b64 {%0, %1}, %2;" : "=f"(lo), "=f"(hi) : "l"(v));
}
__device__ __forceinline__ u64 fma_f32x2(u64 a, u64 b, u64 c) {
    u64 d;
    asm("fma.rn.f32x2 %0, %1, %2, %3;" : "=l"(d) : "l"(a), "l"(b), "l"(c));
    return d;
}
__device__ __forceinline__ float tanh_fast(float x) {
    float r;
    asm("tanh.approx.f32 %0, %1;" : "=f"(r) : "f"(x));
    return r;
}
__device__ __forceinline__ void prefetch_l2(const void* p) {
    asm volatile("prefetch.global.L2 [%0];" :: "l"(p));
}

// packed pair reduction: two independent sums, one shuffle
__device__ __forceinline__ float pairstep(float a, float b, bool lo, int off)
{
    float send = lo ? b : a;
    float recv = __shfl_xor_sync(0xffffffffu, send, off);
    return (lo ? a : b) + recv;
}

// ---------------------------------------------------------------------------
// Main: grid=(74, 8), block=256 (8 warps), 4 CTAs/SM — one wave.
// PDL: unit-0 loads + L2 prefetch of units 1-2 + bias load all BEFORE
// cudaGridDependencySynchronize().
// ---------------------------------------------------------------------------
__global__ void __launch_bounds__(256, 4)
torgb_main_kernel(const float* __restrict__ x,
                  const float* __restrict__ bias,
                  float* __restrict__ out)
{
    const int b    = blockIdx.y;
    const int warp = threadIdx.x >> 5;
    const int lane = threadIdx.x & 31;

    __shared__ __align__(16) float4 kws[CIN];   // 8 KB

    // ---- pointer setup (independent of keff) ----
    const int   p_off  = (lane >> 4) & 1;
    const int   o_idx  = (((lane >> 2) & 1) << 1) | ((lane >> 3) & 1);
    const bool  storer = (lane & 3) == 0;
    const bool  lo16 = lane < 16;
    const bool  lo8  = (lane & 8) == 0;
    const bool  lo4  = (lane & 4) == 0;

    const long long px0 = (long long)b * PIX + (long long)blockIdx.x * UNIT_PX + warp * 2;
    const float4* xp = reinterpret_cast<const float4*>(x + px0 * CIN) + lane;
    float*        op = out + px0 * COUT + p_off * COUT + o_idx;

    const long long xstep = (long long)GRID_X * UNIT_PX * (CIN / 4);
    const long long ostep = (long long)GRID_X * UNIT_PX * COUT;

    // ---- pre-sync: unit-0 register preload (independent of prologue) ----
    float4 a[4], c4[4];
    #pragma unroll
    for (int i = 0; i < 4; i++) a[i]  = __ldcs(xp + i * 32);
    #pragma unroll
    for (int i = 0; i < 4; i++) c4[i] = __ldcs(xp + 128 + i * 32);

    // ---- pre-sync: L2 prefetch of units 1 and 2 (fills idle DRAM window) ----
    if (blockIdx.x + GRID_X < UNITS_PER_BATCH) {
        const float4* xn = xp + xstep;
        #pragma unroll
        for (int i = 0; i < 4; i++) { prefetch_l2(xn + i * 32); prefetch_l2(xn + 128 + i * 32); }
    }
    if (blockIdx.x + 2 * GRID_X < UNITS_PER_BATCH) {
        const float4* xn = xp + 2 * xstep;
        #pragma unroll
        for (int i = 0; i < 4; i++) { prefetch_l2(xn + i * 32); prefetch_l2(xn + 128 + i * 32); }
    }

    // ---- pre-sync: bias (independent of prologue) ----
    const float mybias = bias[o_idx];

    // ---- wait for prologue's g_keff writes, then stage keff in smem ----
#if __CUDA_ARCH__ >= 900
    cudaGridDependencySynchronize();
#endif
    {
        const float4* gk = g_keff + b * CIN;
        kws[threadIdx.x]       = gk[threadIdx.x];
        kws[threadIdx.x + 256] = gk[threadIdx.x + 256];
    }
    __syncthreads();

    const ulonglong2* kwl2 = reinterpret_cast<const ulonglong2*>(kws) + lane;

    int u = blockIdx.x;
    #pragma unroll 1
    while (true) {
        // ---- FMA phase: consume preloaded a/c4 (f32x2 packed) ----
        u64 p0a = 0ull, p0b = 0ull, p1a = 0ull, p1b = 0ull;

        #pragma unroll
        for (int i = 0; i < 4; i++) {
            const float av[4] = {a[i].x,  a[i].y,  a[i].z,  a[i].w};
            const float cv[4] = {c4[i].x, c4[i].y, c4[i].z, c4[i].w};
            u64 ap[4], cp[4];
            #pragma unroll
            for (int j = 0; j < 4; j++) {
                ap[j] = pack_f32x2(av[j], av[j]);
                cp[j] = pack_f32x2(cv[j], cv[j]);
            }
            #pragma unroll
            for (int j = 0; j < 4; j++) {
                const ulonglong2 kk = kwl2[(i * 4 + j) * 32];   // LDS.128
                p0a = fma_f32x2(ap[j], kk.x, p0a);
                p0b = fma_f32x2(ap[j], kk.y, p0b);
                p1a = fma_f32x2(cp[j], kk.x, p1a);
                p1b = fma_f32x2(cp[j], kk.y, p1b);
            }
        }

        // ---- rotation: next unit's loads before the reduce chain ----
        const bool more = (u + GRID_X) < UNITS_PER_BATCH;
        xp += xstep;
        if (more) {
            #pragma unroll
            for (int i = 0; i < 4; i++) a[i]  = __ldcs(xp + i * 32);
            #pragma unroll
            for (int i = 0; i < 4; i++) c4[i] = __ldcs(xp + 128 + i * 32);
        }

        float v0, v1, v2, v3, v4, v5, v6, v7;
        unpack_f32x2(v0, v1, p0a);
        unpack_f32x2(v2, v3, p0b);
        unpack_f32x2(v4, v5, p1a);
        unpack_f32x2(v6, v7, p1b);

        // ---- packed butterfly: 8 sums in 9 shuffles (verified) ----
        float r0 = pairstep(v0, v4, lo16, 16);
        float r1 = pairstep(v1, v5, lo16, 16);
        float r2 = pairstep(v2, v6, lo16, 16);
        float r3 = pairstep(v3, v7, lo16, 16);

        float s0 = pairstep(r0, r1, lo8, 8);
        float s1 = pairstep(r2, r3, lo8, 8);

        float t  = pairstep(s0, s1, lo4, 4);
        t += __shfl_xor_sync(0xffffffffu, t, 2);
        t += __shfl_xor_sync(0xffffffffu, t, 1);

        if (storer)
            *op = tanh_fast(t + mybias);

        if (!more) break;
        op += ostep;
        u  += GRID_X;
    }
}

// ---------------------------------------------------------------------------
// inputs: x[8,128,128,512], w[8,128], affine_w[128,512], affine_b[512],
//         kernel[1,1,512,4], bias[4]  -> out[8,128,128,4] f32
// ---------------------------------------------------------------------------
extern "C" void kernel_launch(void* const* d_in, const int* in_sizes, int n_in,
                              void* d_out, int out_size)
{
    const float* x        = (const float*)d_in[0];
    const float* w        = (const float*)d_in[1];
    const float* affine_w = (const float*)d_in[2];
    const float* affine_b = (const float*)d_in[3];
    const float* k2d      = (const float*)d_in[4];
    const float* bias     = (const float*)d_in[5];
    float*       out      = (float*)d_out;

    dim3 pgrid(B_, 8), pblock(64, 8);
    build_keff_kernel<<<pgrid, pblock>>>(w, affine_w, affine_b, k2d);

    // main kernel with programmatic dependent launch (overlaps prologue tail)
    cudaLaunchConfig_t cfg = {};
    cfg.gridDim  = dim3(GRID_X, B_);
    cfg.blockDim = dim3(256);
    cfg.dynamicSmemBytes = 0;
    cfg.stream = 0;
    cudaLaunchAttribute at[1];
    at[0].id = cudaLaunchAttributeProgrammaticStreamSerialization;
    at[0].val.programmaticStreamSerializationAllowed = 1;
    cfg.attrs = at;
    cfg.numAttrs = 1;
    cudaLaunchKernelEx(&cfg, torgb_main_kernel, x, bias, out);
}